// round 8
// baseline (speedup 1.0000x reference)
#include <cuda_runtime.h>
#include <cstdint>

// Problem constants: N nodes, E edges, D=64 feature dim.
#define NN 50000
#define NE 800000
#define DD 64

// ---------------- device scratch (zero-initialized at module load;
// final_kernel re-zeroes after each use -> deterministic across replays) ----
__device__ float g_sum[NN];          // segment sum of exp(score)
__device__ float g_acc[NN * DD];     // output accumulator (RED target)

// ---------------- helpers ----------------
// two independent reductions within a 16-lane half-warp (offsets <16 stay in-half)
__device__ __forceinline__ void half_sum2(float& a, float& b) {
#pragma unroll
    for (int o = 8; o; o >>= 1) {
        float ta = __shfl_xor_sync(0xffffffffu, a, o);
        float tb = __shfl_xor_sync(0xffffffffu, b, o);
        a += ta; b += tb;
    }
}
__device__ __forceinline__ float half_sum(float v) {
#pragma unroll
    for (int o = 8; o; o >>= 1) v += __shfl_xor_sync(0xffffffffu, v, o);
    return v;
}

// streaming (evict-first) float4 load for use-once weight rows
__device__ __forceinline__ float4 ldcs4(const float4* p) {
    float4 r;
    asm volatile("ld.global.cs.v4.f32 {%0, %1, %2, %3}, [%4];"
                 : "=f"(r.x), "=f"(r.y), "=f"(r.z), "=f"(r.w) : "l"(p));
    return r;
}

// ---------------- kernels ----------------
// Half-warp (16 lanes, float4 each) per edge: key FFN + LN + dot(query[dst]);
// ex = exp(dot) -> attn[e]; segment sum atomic. (No max-subtraction: scores
// ~N(0,8), expf overflows only past ~88 = 11 sigma.)
__global__ __launch_bounds__(256) void key_kernel(
    const float4* __restrict__ feat, const float4* __restrict__ query,
    const int* __restrict__ src, const int* __restrict__ dst,
    const float4* __restrict__ skw, const float4* __restrict__ skb,
    const float4* __restrict__ dkw, const float4* __restrict__ dkb,
    const float4* __restrict__ ekw, const float4* __restrict__ ekb,
    const float4* __restrict__ kgam, const float4* __restrict__ kbet,
    float* __restrict__ attn)
{
    int gtid = blockIdx.x * blockDim.x + threadIdx.x;
    int warp = gtid >> 5;
    int lane = threadIdx.x & 31;
    int lh   = lane & 15;                  // lane within half
    int e    = warp * 2 + (lane >> 4);     // edge for this half
    if (e >= NE) return;

    const int s = __ldg(src + e);
    const int d = __ldg(dst + e);

    float4 u  = __ldg(feat + s * 16 + lh);
    float4 v  = __ldg(feat + d * 16 + lh);
    float4 w1 = ldcs4(skw + (size_t)e * 16 + lh);
    float4 b1 = ldcs4(skb + (size_t)e * 16 + lh);
    float4 w2 = ldcs4(dkw + (size_t)e * 16 + lh);
    float4 b2 = ldcs4(dkb + (size_t)e * 16 + lh);
    float4 w3 = ldcs4(ekw + (size_t)e * 16 + lh);
    float4 b3 = ldcs4(ekb + (size_t)e * 16 + lh);

    float h0 = fmaf(u.x, w1.x, b1.x) + fmaf(v.x, w2.x, b2.x);
    float h1 = fmaf(u.y, w1.y, b1.y) + fmaf(v.y, w2.y, b2.y);
    float h2 = fmaf(u.z, w1.z, b1.z) + fmaf(v.z, w2.z, b2.z);
    float h3 = fmaf(u.w, w1.w, b1.w) + fmaf(v.w, w2.w, b2.w);
    h0 = fmaxf(h0, 0.f); h1 = fmaxf(h1, 0.f);
    h2 = fmaxf(h2, 0.f); h3 = fmaxf(h3, 0.f);
    h0 = fmaf(h0, w3.x, b3.x); h1 = fmaf(h1, w3.y, b3.y);
    h2 = fmaf(h2, w3.z, b3.z); h3 = fmaf(h3, w3.w, b3.w);

    float sum = h0 + h1 + h2 + h3;
    float sq  = h0 * h0 + h1 * h1 + h2 * h2 + h3 * h3;
    half_sum2(sum, sq);
    float mu  = sum * (1.f / 64.f);
    float var = sq * (1.f / 64.f) - mu * mu;
    float rs  = rsqrtf(var + 1e-5f);

    float4 g  = __ldg(kgam + lh);
    float4 be = __ldg(kbet + lh);
    float k0 = fmaf((h0 - mu) * rs, g.x, be.x);
    float k1 = fmaf((h1 - mu) * rs, g.y, be.y);
    float k2 = fmaf((h2 - mu) * rs, g.z, be.z);
    float k3 = fmaf((h3 - mu) * rs, g.w, be.w);

    float4 q = __ldg(query + d * 16 + lh);
    float dot = half_sum(k0 * q.x + k1 * q.y + k2 * q.z + k3 * q.w);

    if (lh == 0) {
        float ex = __expf(dot);
        attn[e] = ex;                        // un-normalized
        atomicAdd(&g_sum[d], ex);
    }
}

// Half-warp per edge: value FFN + LN, weight by ex, red.v4 into g_acc[dst];
// also normalizes attn[e] in place (g_sum is complete after key pass).
__global__ __launch_bounds__(256) void value_kernel(
    const float4* __restrict__ feat,
    const int* __restrict__ src, const int* __restrict__ dst,
    const float4* __restrict__ svw, const float4* __restrict__ svb,
    const float4* __restrict__ dvw, const float4* __restrict__ dvb,
    const float4* __restrict__ evw, const float4* __restrict__ evb,
    const float4* __restrict__ vgam, const float4* __restrict__ vbet,
    float* __restrict__ attn)
{
    int gtid = blockIdx.x * blockDim.x + threadIdx.x;
    int warp = gtid >> 5;
    int lane = threadIdx.x & 31;
    int lh   = lane & 15;
    int e    = warp * 2 + (lane >> 4);
    if (e >= NE) return;

    const int s = __ldg(src + e);
    const int d = __ldg(dst + e);

    float ex = __ldg(attn + e);

    float4 u  = __ldg(feat + s * 16 + lh);
    float4 v  = __ldg(feat + d * 16 + lh);
    float4 w1 = ldcs4(svw + (size_t)e * 16 + lh);
    float4 b1 = ldcs4(svb + (size_t)e * 16 + lh);
    float4 w2 = ldcs4(dvw + (size_t)e * 16 + lh);
    float4 b2 = ldcs4(dvb + (size_t)e * 16 + lh);
    float4 w3 = ldcs4(evw + (size_t)e * 16 + lh);
    float4 b3 = ldcs4(evb + (size_t)e * 16 + lh);

    float h0 = fmaf(u.x, w1.x, b1.x) + fmaf(v.x, w2.x, b2.x);
    float h1 = fmaf(u.y, w1.y, b1.y) + fmaf(v.y, w2.y, b2.y);
    float h2 = fmaf(u.z, w1.z, b1.z) + fmaf(v.z, w2.z, b2.z);
    float h3 = fmaf(u.w, w1.w, b1.w) + fmaf(v.w, w2.w, b2.w);
    h0 = fmaxf(h0, 0.f); h1 = fmaxf(h1, 0.f);
    h2 = fmaxf(h2, 0.f); h3 = fmaxf(h3, 0.f);
    h0 = fmaf(h0, w3.x, b3.x); h1 = fmaf(h1, w3.y, b3.y);
    h2 = fmaf(h2, w3.z, b3.z); h3 = fmaf(h3, w3.w, b3.w);

    float sum = h0 + h1 + h2 + h3;
    float sq  = h0 * h0 + h1 * h1 + h2 * h2 + h3 * h3;
    half_sum2(sum, sq);
    float mu  = sum * (1.f / 64.f);
    float var = sq * (1.f / 64.f) - mu * mu;
    float rs  = rsqrtf(var + 1e-5f);

    float4 vg = __ldg(vgam + lh);
    float4 vb = __ldg(vbet + lh);
    float v0 = fmaf((h0 - mu) * rs, vg.x, vb.x) * ex;
    float v1 = fmaf((h1 - mu) * rs, vg.y, vb.y) * ex;
    float v2 = fmaf((h2 - mu) * rs, vg.z, vb.z) * ex;
    float v3 = fmaf((h3 - mu) * rs, vg.w, vb.w) * ex;

    // vector reduction into g_acc[d*64 + lh*4 .. +3]
    float* dst_p = g_acc + (size_t)d * DD + lh * 4;
    asm volatile("red.global.add.v4.f32 [%0], {%1, %2, %3, %4};"
                 :: "l"(dst_p), "f"(v0), "f"(v1), "f"(v2), "f"(v3) : "memory");
    if (lh == 0) {
        float sden = g_sum[d];
        float inv = (sden > 0.f) ? __frcp_rn(sden) : 0.f;
        attn[e] = ex * inv;                  // final normalized attention
    }
}

// Half-warp (16 lanes, float4) per node: divide by seg sum, output LayerNorm
// into d_out, then zero g_acc row + g_sum entry for the next launch.
__global__ __launch_bounds__(256) void final_kernel(
    const float4* __restrict__ agam, const float4* __restrict__ abet,
    float4* __restrict__ out)
{
    int gtid = blockIdx.x * blockDim.x + threadIdx.x;
    int warp = gtid >> 5;
    int lane = threadIdx.x & 31;
    int lh   = lane & 15;
    int n    = warp * 2 + (lane >> 4);
    if (n >= NN) return;

    float4* accp = (float4*)(g_acc + (size_t)n * DD) + lh;
    float4 a = *accp;
    float sden = g_sum[n];
    float inv = (sden > 0.f) ? __frcp_rn(sden) : 0.f;
    float o0 = a.x * inv, o1 = a.y * inv, o2 = a.z * inv, o3 = a.w * inv;

    float sum = o0 + o1 + o2 + o3;
    float sq  = o0 * o0 + o1 * o1 + o2 * o2 + o3 * o3;
    half_sum2(sum, sq);
    float mu  = sum * (1.f / 64.f);
    float var = sq * (1.f / 64.f) - mu * mu;
    float rs  = rsqrtf(var + 1e-5f);

    float4 ag = __ldg(agam + lh);
    float4 ab = __ldg(abet + lh);
    float4 o;
    o.x = fmaf((o0 - mu) * rs, ag.x, ab.x);
    o.y = fmaf((o1 - mu) * rs, ag.y, ab.y);
    o.z = fmaf((o2 - mu) * rs, ag.z, ab.z);
    o.w = fmaf((o3 - mu) * rs, ag.w, ab.w);
    out[(size_t)n * 16 + lh] = o;

    // self-clean for next launch (determinism across graph replays)
    *accp = make_float4(0.f, 0.f, 0.f, 0.f);
    if (lh == 0) g_sum[n] = 0.f;
}

// ---------------- launch ----------------
extern "C" void kernel_launch(void* const* d_in, const int* in_sizes, int n_in,
                              void* d_out, int out_size)
{
    const float4* feat  = (const float4*)d_in[0];
    const float4* query = (const float4*)d_in[1];
    const int*    src   = (const int*)d_in[2];
    const int*    dst   = (const int*)d_in[3];
    const float4* skw = (const float4*)d_in[4];
    const float4* skb = (const float4*)d_in[5];
    const float4* dkw = (const float4*)d_in[6];
    const float4* dkb = (const float4*)d_in[7];
    const float4* ekw = (const float4*)d_in[8];
    const float4* ekb = (const float4*)d_in[9];
    const float4* svw = (const float4*)d_in[10];
    const float4* svb = (const float4*)d_in[11];
    const float4* dvw = (const float4*)d_in[12];
    const float4* dvb = (const float4*)d_in[13];
    const float4* evw = (const float4*)d_in[14];
    const float4* evb = (const float4*)d_in[15];
    const float4* kgam = (const float4*)d_in[16];
    const float4* kbet = (const float4*)d_in[17];
    const float4* vgam = (const float4*)d_in[18];
    const float4* vbet = (const float4*)d_in[19];
    const float4* agam = (const float4*)d_in[20];
    const float4* abet = (const float4*)d_in[21];

    float* out_f = (float*)d_out;                 // [N, D] first
    float* attn  = out_f + (size_t)NN * DD;       // then [E, 1]

    // 2 edges per warp -> NE/2 warps -> NE*16 threads
    const int big_grid = (NE * 16 + 255) / 256;   // 50000 blocks

    key_kernel<<<big_grid, 256>>>(feat, query, src, dst,
                                  skw, skb, dkw, dkb, ekw, ekb,
                                  kgam, kbet, attn);
    value_kernel<<<big_grid, 256>>>(feat, src, dst,
                                    svw, svb, dvw, dvb, evw, evb,
                                    vgam, vbet, attn);
    final_kernel<<<(NN * 16 + 255) / 256, 256>>>(agam, abet, (float4*)out_f);
}

// round 9
// speedup vs baseline: 1.1172x; 1.1172x over previous
#include <cuda_runtime.h>
#include <cstdint>

// Problem constants: N nodes, E edges, D=64 feature dim.
#define NN 50000
#define NE 800000
#define DD 64

// ---------------- device scratch ----------------
__device__ float g_sum[NN];     // segment sum of exp(score)

// ---------------- helpers ----------------
// two independent reductions within a 16-lane half-warp (offsets <16 stay in-half)
__device__ __forceinline__ void half_sum2(float& a, float& b) {
#pragma unroll
    for (int o = 8; o; o >>= 1) {
        float ta = __shfl_xor_sync(0xffffffffu, a, o);
        float tb = __shfl_xor_sync(0xffffffffu, b, o);
        a += ta; b += tb;
    }
}
__device__ __forceinline__ float half_sum(float v) {
#pragma unroll
    for (int o = 8; o; o >>= 1) v += __shfl_xor_sync(0xffffffffu, v, o);
    return v;
}

// streaming (evict-first) float4 load for use-once weight rows
__device__ __forceinline__ float4 ldcs4(const float4* p) {
    float4 r;
    asm volatile("ld.global.cs.v4.f32 {%0, %1, %2, %3}, [%4];"
                 : "=f"(r.x), "=f"(r.y), "=f"(r.z), "=f"(r.w) : "l"(p));
    return r;
}

// ---------------- kernels ----------------
__global__ __launch_bounds__(256) void init_kernel(float4* __restrict__ out4) {
    int i = blockIdx.x * blockDim.x + threadIdx.x;
    int stride = gridDim.x * blockDim.x;
    const float4 z = make_float4(0.f, 0.f, 0.f, 0.f);
    for (int k = i; k < NN * DD / 4; k += stride) out4[k] = z;
    for (int k = i; k < NN; k += stride) g_sum[k] = 0.f;
}

// Half-warp (16 lanes, float4 each) per edge: key FFN + LN + dot(query[dst]);
// ex = exp(dot) -> attn[e]; segment sum atomic. (No max-subtraction: scores
// ~N(0,8), expf overflows only past ~88 = 11 sigma.)
__global__ __launch_bounds__(256) void key_kernel(
    const float4* __restrict__ feat, const float4* __restrict__ query,
    const int* __restrict__ src, const int* __restrict__ dst,
    const float4* __restrict__ skw, const float4* __restrict__ skb,
    const float4* __restrict__ dkw, const float4* __restrict__ dkb,
    const float4* __restrict__ ekw, const float4* __restrict__ ekb,
    const float4* __restrict__ kgam, const float4* __restrict__ kbet,
    float* __restrict__ attn)
{
    int gtid = blockIdx.x * blockDim.x + threadIdx.x;
    int warp = gtid >> 5;
    int lane = threadIdx.x & 31;
    int lh   = lane & 15;                  // lane within half
    int e    = warp * 2 + (lane >> 4);     // edge for this half
    if (e >= NE) return;

    const int s = __ldg(src + e);
    const int d = __ldg(dst + e);

    float4 u  = __ldg(feat + s * 16 + lh);
    float4 v  = __ldg(feat + d * 16 + lh);
    float4 w1 = ldcs4(skw + (size_t)e * 16 + lh);
    float4 b1 = ldcs4(skb + (size_t)e * 16 + lh);
    float4 w2 = ldcs4(dkw + (size_t)e * 16 + lh);
    float4 b2 = ldcs4(dkb + (size_t)e * 16 + lh);
    float4 w3 = ldcs4(ekw + (size_t)e * 16 + lh);
    float4 b3 = ldcs4(ekb + (size_t)e * 16 + lh);

    float h0 = fmaf(u.x, w1.x, b1.x) + fmaf(v.x, w2.x, b2.x);
    float h1 = fmaf(u.y, w1.y, b1.y) + fmaf(v.y, w2.y, b2.y);
    float h2 = fmaf(u.z, w1.z, b1.z) + fmaf(v.z, w2.z, b2.z);
    float h3 = fmaf(u.w, w1.w, b1.w) + fmaf(v.w, w2.w, b2.w);
    h0 = fmaxf(h0, 0.f); h1 = fmaxf(h1, 0.f);
    h2 = fmaxf(h2, 0.f); h3 = fmaxf(h3, 0.f);
    h0 = fmaf(h0, w3.x, b3.x); h1 = fmaf(h1, w3.y, b3.y);
    h2 = fmaf(h2, w3.z, b3.z); h3 = fmaf(h3, w3.w, b3.w);

    float sum = h0 + h1 + h2 + h3;
    float sq  = h0 * h0 + h1 * h1 + h2 * h2 + h3 * h3;
    half_sum2(sum, sq);
    float mu  = sum * (1.f / 64.f);
    float var = sq * (1.f / 64.f) - mu * mu;
    float rs  = rsqrtf(var + 1e-5f);

    float4 g  = __ldg(kgam + lh);
    float4 be = __ldg(kbet + lh);
    float k0 = fmaf((h0 - mu) * rs, g.x, be.x);
    float k1 = fmaf((h1 - mu) * rs, g.y, be.y);
    float k2 = fmaf((h2 - mu) * rs, g.z, be.z);
    float k3 = fmaf((h3 - mu) * rs, g.w, be.w);

    float4 q = __ldg(query + d * 16 + lh);
    float dot = half_sum(k0 * q.x + k1 * q.y + k2 * q.z + k3 * q.w);

    if (lh == 0) {
        float ex = __expf(dot);
        attn[e] = ex;                        // un-normalized
        atomicAdd(&g_sum[d], ex);
    }
}

// Half-warp per edge: value FFN + LN, weight by ex, red.v4 into out[dst];
// also normalizes attn[e] in place (g_sum is complete after key pass).
__global__ __launch_bounds__(256) void value_kernel(
    const float4* __restrict__ feat,
    const int* __restrict__ src, const int* __restrict__ dst,
    const float4* __restrict__ svw, const float4* __restrict__ svb,
    const float4* __restrict__ dvw, const float4* __restrict__ dvb,
    const float4* __restrict__ evw, const float4* __restrict__ evb,
    const float4* __restrict__ vgam, const float4* __restrict__ vbet,
    float* __restrict__ out, float* __restrict__ attn)
{
    int gtid = blockIdx.x * blockDim.x + threadIdx.x;
    int warp = gtid >> 5;
    int lane = threadIdx.x & 31;
    int lh   = lane & 15;
    int e    = warp * 2 + (lane >> 4);
    if (e >= NE) return;

    const int s = __ldg(src + e);
    const int d = __ldg(dst + e);

    float ex = __ldg(attn + e);

    float4 u  = __ldg(feat + s * 16 + lh);
    float4 v  = __ldg(feat + d * 16 + lh);
    float4 w1 = ldcs4(svw + (size_t)e * 16 + lh);
    float4 b1 = ldcs4(svb + (size_t)e * 16 + lh);
    float4 w2 = ldcs4(dvw + (size_t)e * 16 + lh);
    float4 b2 = ldcs4(dvb + (size_t)e * 16 + lh);
    float4 w3 = ldcs4(evw + (size_t)e * 16 + lh);
    float4 b3 = ldcs4(evb + (size_t)e * 16 + lh);

    float h0 = fmaf(u.x, w1.x, b1.x) + fmaf(v.x, w2.x, b2.x);
    float h1 = fmaf(u.y, w1.y, b1.y) + fmaf(v.y, w2.y, b2.y);
    float h2 = fmaf(u.z, w1.z, b1.z) + fmaf(v.z, w2.z, b2.z);
    float h3 = fmaf(u.w, w1.w, b1.w) + fmaf(v.w, w2.w, b2.w);
    h0 = fmaxf(h0, 0.f); h1 = fmaxf(h1, 0.f);
    h2 = fmaxf(h2, 0.f); h3 = fmaxf(h3, 0.f);
    h0 = fmaf(h0, w3.x, b3.x); h1 = fmaf(h1, w3.y, b3.y);
    h2 = fmaf(h2, w3.z, b3.z); h3 = fmaf(h3, w3.w, b3.w);

    float sum = h0 + h1 + h2 + h3;
    float sq  = h0 * h0 + h1 * h1 + h2 * h2 + h3 * h3;
    half_sum2(sum, sq);
    float mu  = sum * (1.f / 64.f);
    float var = sq * (1.f / 64.f) - mu * mu;
    float rs  = rsqrtf(var + 1e-5f);

    float4 vg = __ldg(vgam + lh);
    float4 vb = __ldg(vbet + lh);
    float v0 = fmaf((h0 - mu) * rs, vg.x, vb.x) * ex;
    float v1 = fmaf((h1 - mu) * rs, vg.y, vb.y) * ex;
    float v2 = fmaf((h2 - mu) * rs, vg.z, vb.z) * ex;
    float v3 = fmaf((h3 - mu) * rs, vg.w, vb.w) * ex;

    // vector reduction into out[d*64 + lh*4 .. +3]
    float* dst_p = out + (size_t)d * DD + lh * 4;
    asm volatile("red.global.add.v4.f32 [%0], {%1, %2, %3, %4};"
                 :: "l"(dst_p), "f"(v0), "f"(v1), "f"(v2), "f"(v3) : "memory");
    if (lh == 0) {
        float sden = g_sum[d];
        float inv = (sden > 0.f) ? __frcp_rn(sden) : 0.f;
        attn[e] = ex * inv;                  // final normalized attention
    }
}

// Half-warp (16 lanes, float4) per node: divide by seg sum, output LayerNorm
// in place on d_out.
__global__ __launch_bounds__(256) void final_kernel(
    const float4* __restrict__ agam, const float4* __restrict__ abet,
    float4* __restrict__ out)
{
    int gtid = blockIdx.x * blockDim.x + threadIdx.x;
    int warp = gtid >> 5;
    int lane = threadIdx.x & 31;
    int lh   = lane & 15;
    int n    = warp * 2 + (lane >> 4);
    if (n >= NN) return;

    float4 a = out[(size_t)n * 16 + lh];
    float sden = g_sum[n];
    float inv = (sden > 0.f) ? __frcp_rn(sden) : 0.f;
    float o0 = a.x * inv, o1 = a.y * inv, o2 = a.z * inv, o3 = a.w * inv;

    float sum = o0 + o1 + o2 + o3;
    float sq  = o0 * o0 + o1 * o1 + o2 * o2 + o3 * o3;
    half_sum2(sum, sq);
    float mu  = sum * (1.f / 64.f);
    float var = sq * (1.f / 64.f) - mu * mu;
    float rs  = rsqrtf(var + 1e-5f);

    float4 ag = __ldg(agam + lh);
    float4 ab = __ldg(abet + lh);
    float4 o;
    o.x = fmaf((o0 - mu) * rs, ag.x, ab.x);
    o.y = fmaf((o1 - mu) * rs, ag.y, ab.y);
    o.z = fmaf((o2 - mu) * rs, ag.z, ab.z);
    o.w = fmaf((o3 - mu) * rs, ag.w, ab.w);
    out[(size_t)n * 16 + lh] = o;
}

// ---------------- launch ----------------
extern "C" void kernel_launch(void* const* d_in, const int* in_sizes, int n_in,
                              void* d_out, int out_size)
{
    const float4* feat  = (const float4*)d_in[0];
    const float4* query = (const float4*)d_in[1];
    const int*    src   = (const int*)d_in[2];
    const int*    dst   = (const int*)d_in[3];
    const float4* skw = (const float4*)d_in[4];
    const float4* skb = (const float4*)d_in[5];
    const float4* dkw = (const float4*)d_in[6];
    const float4* dkb = (const float4*)d_in[7];
    const float4* ekw = (const float4*)d_in[8];
    const float4* ekb = (const float4*)d_in[9];
    const float4* svw = (const float4*)d_in[10];
    const float4* svb = (const float4*)d_in[11];
    const float4* dvw = (const float4*)d_in[12];
    const float4* dvb = (const float4*)d_in[13];
    const float4* evw = (const float4*)d_in[14];
    const float4* evb = (const float4*)d_in[15];
    const float4* kgam = (const float4*)d_in[16];
    const float4* kbet = (const float4*)d_in[17];
    const float4* vgam = (const float4*)d_in[18];
    const float4* vbet = (const float4*)d_in[19];
    const float4* agam = (const float4*)d_in[20];
    const float4* abet = (const float4*)d_in[21];

    float* out_f = (float*)d_out;                 // [N, D] first
    float* attn  = out_f + (size_t)NN * DD;       // then [E, 1]

    // 2 edges per warp -> NE/2 warps -> NE*16 threads
    const int big_grid = (NE * 16 + 255) / 256;   // 50000 blocks

    init_kernel<<<592, 256>>>((float4*)out_f);
    key_kernel<<<big_grid, 256>>>(feat, query, src, dst,
                                  skw, skb, dkw, dkb, ekw, ekb,
                                  kgam, kbet, attn);
    value_kernel<<<big_grid, 256>>>(feat, src, dst,
                                    svw, svb, dvw, dvb, evw, evb,
                                    vgam, vbet, out_f, attn);
    final_kernel<<<(NN * 16 + 255) / 256, 256>>>(agam, abet, (float4*)out_f);
}